// round 13
// baseline (speedup 1.0000x reference)
#include <cuda_runtime.h>
#include <cstdint>

// ---------------- problem constants ----------------
#define NROWS   8192
#define KDIM    4096
#define ODIM    4096
#define KW      (KDIM / 32)        // 128 words of packed sign bits per row
#define TW      128                // output tile: 128 x 128
#define CHUNK   16                 // k-words per pipeline stage
#define KITC    (KW / CHUNK)       // 8 chunks
#define XST_WORDS (2 * CHUNK * TW)              // A + B: 4096 words = 16KB
#define SMEM_BYTES  (4 * XST_WORDS * 4)         // 65536

// ---------------- device scratch (allocation-free rule) ----------------
__device__ __align__(1024) uint32_t g_xT[(size_t)KW * NROWS];
__device__ __align__(1024) uint32_t g_wT[(size_t)KW * ODIM];

// ---------------- helpers ----------------
__device__ __forceinline__ uint32_t smem_u32(const void* p) {
    uint32_t a;
    asm("{ .reg .u64 t; cvta.to.shared.u64 t, %1; cvt.u32.u64 %0, t; }" : "=r"(a) : "l"(p));
    return a;
}
#define CP_ASYNC16(dst, src) \
    asm volatile("cp.async.cg.shared.global [%0], [%1], 16;" :: "r"(dst), "l"(src))
#define CP_COMMIT() asm volatile("cp.async.commit_group;" ::: "memory")
#define CP_WAIT3()  asm volatile("cp.async.wait_group 3;"  ::: "memory")

__device__ __forceinline__ uint32_t xor3(uint32_t a, uint32_t b, uint32_t c) {
    uint32_t d; asm("lop3.b32 %0, %1, %2, %3, 0x96;" : "=r"(d) : "r"(a), "r"(b), "r"(c));
    return d;
}
__device__ __forceinline__ uint32_t maj3(uint32_t a, uint32_t b, uint32_t c) {
    uint32_t d; asm("lop3.b32 %0, %1, %2, %3, 0xE8;" : "=r"(d) : "r"(a), "r"(b), "r"(c));
    return d;
}

// ------- pack: f32 -> 1 bit sign, transposed [kw][row]; x and w fused -------
// 2 rows per thread (same kw) -> 16 LDG.128 MLP, uint2 store
__global__ void __launch_bounds__(256) pack_bits(const float4* __restrict__ x,
                                                 uint32_t* __restrict__ xT,
                                                 const float4* __restrict__ w,
                                                 uint32_t* __restrict__ wT) {
    const int b = blockIdx.x;
    const float4* in;
    uint32_t* outT;
    int nhs, lb;
    if (b < 2048) { in = x; outT = xT; nhs = 12; lb = b; }          // 8192 rows
    else          { in = w; outT = wT; nhs = 11; lb = b - 2048; }   // 4096 rows
    const int idx = lb * 256 + threadIdx.x;          // word-pair index
    const int kw  = idx >> nhs;
    const int n   = (idx & ((1 << nhs) - 1)) * 2;

    uint32_t wo[2];
    #pragma unroll
    for (int rr = 0; rr < 2; rr++) {
        const float4* p = in + (size_t)(n + rr) * (KDIM / 4) + kw * 8;
        uint32_t v = 0;
        #pragma unroll
        for (int j = 0; j < 8; j++) {
            float4 f = p[j];
            v |= (__float_as_uint(f.x) >> 31) << (4 * j);
            v |= (__float_as_uint(f.y) >> 31) << (4 * j + 1);
            v |= (__float_as_uint(f.z) >> 31) << (4 * j + 2);
            v |= (__float_as_uint(f.w) >> 31) << (4 * j + 3);
        }
        wo[rr] = v;
    }
    *reinterpret_cast<uint2*>(outT + (size_t)kw * (2 << nhs) + n) = make_uint2(wo[0], wo[1]);
}

// ---- XNOR GEMM: g0 = CSA 8:4, g1 = level-1 (ALU->POPC rebalance), R5 base ----
// out[n][o] = 4096 - 2 * sum_kw popc(xT[kw][n] ^ wT[kw][o]) + bias[o]
__global__ void __launch_bounds__(256, 1) xnor_gemm(
    const uint32_t* __restrict__ xT, const uint32_t* __restrict__ wT,
    const float* __restrict__ bias, float* __restrict__ out)
{
    extern __shared__ __align__(16) uint32_t sm[];
    const uint32_t smBase = smem_u32(sm);
    const int tid = threadIdx.x;
    const int tx  = tid & 15;        // 16 col groups
    const int ty  = tid >> 4;        // 16 row groups
    const int mt  = blockIdx.x & 63;
    const int nt  = blockIdx.x >> 6;
    const int mBase = mt * TW;
    const int nBase = nt * TW;

    auto load_stage = [&](int s, int c) {
        #pragma unroll
        for (int k = 0; k < 4; k++) {
            const int ch  = tid + k * 256;
            const int tsr = ch >> 9;
            const int rem = ch & 511;
            const int kw  = rem >> 5;
            const int nq  = rem & 31;
            const uint32_t* gsrc = tsr
                ? (wT + (size_t)(c * CHUNK + kw) * ODIM  + nBase + nq * 4)
                : (xT + (size_t)(c * CHUNK + kw) * NROWS + mBase + nq * 4);
            const uint32_t dst = smBase +
                (uint32_t)((s * XST_WORDS + tsr * 2048 + kw * TW + nq * 4) * 4);
            CP_ASYNC16(dst, gsrc);
        }
    };

    int acc[8][8];
    #pragma unroll
    for (int r = 0; r < 8; r++)
        #pragma unroll
        for (int c = 0; c < 8; c++) acc[r][c] = 0;

    #pragma unroll
    for (int s = 0; s < 3; s++) { load_stage(s, s); CP_COMMIT(); }

    #pragma unroll 1
    for (int c = 0; c < KITC; c++) {
        const int cl = c + 3;
        if (cl < KITC) load_stage(cl & 3, cl);
        CP_COMMIT();
        CP_WAIT3();
        __syncthreads();

        const uint32_t* As = sm + (c & 3) * XST_WORDS;
        const uint32_t* Bs = As + 2048;

        #pragma unroll
        for (int g = 0; g < 2; g++) {
            const int kb = g * 8;

            uint32_t Bf[8][8];
            #pragma unroll
            for (int k = 0; k < 8; k++) {
                uint4 u0 = *reinterpret_cast<const uint4*>(Bs + (kb + k) * TW + tx * 8);
                uint4 u1 = *reinterpret_cast<const uint4*>(Bs + (kb + k) * TW + tx * 8 + 4);
                Bf[k][0] = u0.x; Bf[k][1] = u0.y; Bf[k][2] = u0.z; Bf[k][3] = u0.w;
                Bf[k][4] = u1.x; Bf[k][5] = u1.y; Bf[k][6] = u1.z; Bf[k][7] = u1.w;
            }

            #pragma unroll
            for (int rr = 0; rr < 2; rr++) {
                uint32_t Af[8][4];
                #pragma unroll
                for (int k = 0; k < 8; k++) {
                    uint4 u = *reinterpret_cast<const uint4*>(
                        As + (kb + k) * TW + ty * 8 + rr * 4);
                    Af[k][0] = u.x; Af[k][1] = u.y; Af[k][2] = u.z; Af[k][3] = u.w;
                }
                #pragma unroll
                for (int r = 0; r < 4; r++) {
                    #pragma unroll
                    for (int cc = 0; cc < 8; cc++) {
                        const uint32_t x0 = Af[0][r] ^ Bf[0][cc];
                        const uint32_t x1 = Af[1][r] ^ Bf[1][cc];
                        const uint32_t x2 = Af[2][r] ^ Bf[2][cc];
                        const uint32_t x3 = Af[3][r] ^ Bf[3][cc];
                        const uint32_t x4 = Af[4][r] ^ Bf[4][cc];
                        const uint32_t x5 = Af[5][r] ^ Bf[5][cc];
                        const uint32_t x6 = Af[6][r] ^ Bf[6][cc];
                        const uint32_t x7 = Af[7][r] ^ Bf[7][cc];
                        const uint32_t s0 = xor3(x0, x1, x2), c0 = maj3(x0, x1, x2);
                        const uint32_t s1 = xor3(x3, x4, x5), c1 = maj3(x3, x4, x5);
                        const uint32_t s2 = x6 ^ x7,          c2 = x6 & x7;
                        if (g == 0) {
                            // full CSA 8 -> 4 planes (ALU-heavier, POPC-lighter)
                            const uint32_t S  = xor3(s0, s1, s2), C3 = maj3(s0, s1, s2);
                            const uint32_t S2 = xor3(c0, c1, c2), C2 = maj3(c0, c1, c2);
                            acc[rr * 4 + r][cc] += __popc(S)
                                                 + 2 * (__popc(S2) + __popc(C3))
                                                 + 4 * __popc(C2);
                        } else {
                            // level-1: 6 planes (ALU-lighter, POPC-heavier)
                            acc[rr * 4 + r][cc] +=
                                  (__popc(s0) + __popc(s1) + __popc(s2))
                                + 2 * (__popc(c0) + __popc(c1) + __popc(c2));
                        }
                    }
                }
            }
        }
        __syncthreads();
    }

    // -------- epilogue: out = 4096 - 2*count + bias --------
    const int rb = mBase + ty * 8;
    const int cb = nBase + tx * 8;
    const float4 bias0 = *reinterpret_cast<const float4*>(bias + cb);
    const float4 bias1 = *reinterpret_cast<const float4*>(bias + cb + 4);

    #pragma unroll
    for (int r = 0; r < 8; r++) {
        float4 o0, o1;
        o0.x = (float)(KDIM - 2 * acc[r][0]) + bias0.x;
        o0.y = (float)(KDIM - 2 * acc[r][1]) + bias0.y;
        o0.z = (float)(KDIM - 2 * acc[r][2]) + bias0.z;
        o0.w = (float)(KDIM - 2 * acc[r][3]) + bias0.w;
        o1.x = (float)(KDIM - 2 * acc[r][4]) + bias1.x;
        o1.y = (float)(KDIM - 2 * acc[r][5]) + bias1.y;
        o1.z = (float)(KDIM - 2 * acc[r][6]) + bias1.z;
        o1.w = (float)(KDIM - 2 * acc[r][7]) + bias1.w;
        float* po = out + (size_t)(rb + r) * ODIM + cb;
        *reinterpret_cast<float4*>(po)     = o0;
        *reinterpret_cast<float4*>(po + 4) = o1;
    }
}

// ---------------- host ----------------
extern "C" void kernel_launch(void* const* d_in, const int* in_sizes, int n_in,
                              void* d_out, int out_size) {
    const float* x    = (const float*)d_in[0];
    const float* w    = (const float*)d_in[1];
    const float* bias = (const float*)d_in[2];
    float* out = (float*)d_out;

    void* pxT = nullptr; cudaGetSymbolAddress(&pxT, g_xT);
    void* pwT = nullptr; cudaGetSymbolAddress(&pwT, g_wT);

    // fused pack: blocks [0,2048) -> x, [2048,3072) -> w
    pack_bits<<<3072, 256>>>((const float4*)x, (uint32_t*)pxT,
                             (const float4*)w, (uint32_t*)pwT);

    cudaFuncSetAttribute(xnor_gemm, cudaFuncAttributeMaxDynamicSharedMemorySize, SMEM_BYTES);

    const int grid = (NROWS / TW) * (ODIM / TW);   // 2048
    xnor_gemm<<<grid, 256, SMEM_BYTES>>>((const uint32_t*)pxT, (const uint32_t*)pwT,
                                         bias, out);
}

// round 14
// speedup vs baseline: 1.2349x; 1.2349x over previous
#include <cuda_runtime.h>
#include <cstdint>

// ---------------- problem constants ----------------
#define NROWS   8192
#define KDIM    4096
#define ODIM    4096
#define KW      (KDIM / 32)        // 128 words of packed sign bits per row
#define TW      128                // output tile: 128 x 128
#define CHUNK   16                 // k-words per pipeline stage
#define KITC    (KW / CHUNK)       // 8 chunks
#define NTHR    512                // 16 warps -> 4 per SMSP
#define XST_WORDS (2 * CHUNK * TW)              // A + B: 4096 words = 16KB
#define SMEM_BYTES  (4 * XST_WORDS * 4)         // 65536

// ---------------- device scratch (allocation-free rule) ----------------
__device__ __align__(1024) uint32_t g_xT[(size_t)KW * NROWS];
__device__ __align__(1024) uint32_t g_wT[(size_t)KW * ODIM];

// ---------------- helpers ----------------
__device__ __forceinline__ uint32_t smem_u32(const void* p) {
    uint32_t a;
    asm("{ .reg .u64 t; cvta.to.shared.u64 t, %1; cvt.u32.u64 %0, t; }" : "=r"(a) : "l"(p));
    return a;
}
#define CP_ASYNC16(dst, src) \
    asm volatile("cp.async.cg.shared.global [%0], [%1], 16;" :: "r"(dst), "l"(src))
#define CP_COMMIT() asm volatile("cp.async.commit_group;" ::: "memory")
#define CP_WAIT3()  asm volatile("cp.async.wait_group 3;"  ::: "memory")

__device__ __forceinline__ uint32_t xor3(uint32_t a, uint32_t b, uint32_t c) {
    uint32_t d; asm("lop3.b32 %0, %1, %2, %3, 0x96;" : "=r"(d) : "r"(a), "r"(b), "r"(c));
    return d;
}
__device__ __forceinline__ uint32_t maj3(uint32_t a, uint32_t b, uint32_t c) {
    uint32_t d; asm("lop3.b32 %0, %1, %2, %3, 0xE8;" : "=r"(d) : "r"(a), "r"(b), "r"(c));
    return d;
}

// ------- pack: f32 -> 1 bit sign, transposed [kw][row]; x and w fused -------
__global__ void __launch_bounds__(256) pack_bits(const float4* __restrict__ x,
                                                 uint32_t* __restrict__ xT,
                                                 const float4* __restrict__ w,
                                                 uint32_t* __restrict__ wT) {
    const int b = blockIdx.x;
    const float4* in;
    uint32_t* outT;
    int nhs, lb;
    if (b < 2048) { in = x; outT = xT; nhs = 12; lb = b; }          // 8192 rows
    else          { in = w; outT = wT; nhs = 11; lb = b - 2048; }   // 4096 rows
    const int idx = lb * 256 + threadIdx.x;          // word-pair index
    const int kw  = idx >> nhs;
    const int n   = (idx & ((1 << nhs) - 1)) * 2;

    uint32_t wo[2];
    #pragma unroll
    for (int rr = 0; rr < 2; rr++) {
        const float4* p = in + (size_t)(n + rr) * (KDIM / 4) + kw * 8;
        uint32_t v = 0;
        #pragma unroll
        for (int j = 0; j < 8; j++) {
            float4 f = p[j];
            v |= (__float_as_uint(f.x) >> 31) << (4 * j);
            v |= (__float_as_uint(f.y) >> 31) << (4 * j + 1);
            v |= (__float_as_uint(f.z) >> 31) << (4 * j + 2);
            v |= (__float_as_uint(f.w) >> 31) << (4 * j + 3);
        }
        wo[rr] = v;
    }
    *reinterpret_cast<uint2*>(outT + (size_t)kw * (2 << nhs) + n) = make_uint2(wo[0], wo[1]);
}

// --- XNOR GEMM: CSA 8->4, 512 threads (4 warps/SMSP), 8x4 thread tile ----
// out[n][o] = 4096 - 2 * sum_kw popc(xT[kw][n] ^ wT[kw][o]) + bias[o]
__global__ void __launch_bounds__(NTHR, 1) xnor_gemm(
    const uint32_t* __restrict__ xT, const uint32_t* __restrict__ wT,
    const float* __restrict__ bias, float* __restrict__ out)
{
    extern __shared__ __align__(16) uint32_t sm[];
    const uint32_t smBase = smem_u32(sm);
    const int tid = threadIdx.x;
    const int tx  = tid & 31;        // 32 col groups of 4
    const int ty  = tid >> 5;        // 16 row groups of 8
    const int mt  = blockIdx.x & 63;
    const int nt  = blockIdx.x >> 6;
    const int mBase = mt * TW;
    const int nBase = nt * TW;

    auto load_stage = [&](int s, int c) {
        #pragma unroll
        for (int k = 0; k < 2; k++) {
            const int ch  = tid + k * NTHR;      // 0..1023 chunks of 16B
            const int tsr = ch >> 9;
            const int rem = ch & 511;
            const int kw  = rem >> 5;
            const int nq  = rem & 31;
            const uint32_t* gsrc = tsr
                ? (wT + (size_t)(c * CHUNK + kw) * ODIM  + nBase + nq * 4)
                : (xT + (size_t)(c * CHUNK + kw) * NROWS + mBase + nq * 4);
            const uint32_t dst = smBase +
                (uint32_t)((s * XST_WORDS + tsr * 2048 + kw * TW + nq * 4) * 4);
            CP_ASYNC16(dst, gsrc);
        }
    };

    // packed u16x2 accumulators: [row][colpair] (counts <= 4096 fit u16)
    uint32_t accP[8][2];
    #pragma unroll
    for (int r = 0; r < 8; r++) { accP[r][0] = 0; accP[r][1] = 0; }

    #pragma unroll
    for (int s = 0; s < 3; s++) { load_stage(s, s); CP_COMMIT(); }

    #pragma unroll 1
    for (int c = 0; c < KITC; c++) {
        const int cl = c + 3;
        if (cl < KITC) load_stage(cl & 3, cl);
        CP_COMMIT();
        CP_WAIT3();
        __syncthreads();

        const uint32_t* As = sm + (c & 3) * XST_WORDS;
        const uint32_t* Bs = As + 2048;

        // two groups of 8 k-words, each compressed 8 -> 4 popc via CSA tree
        #pragma unroll
        for (int g = 0; g < 2; g++) {
            const int kb = g * 8;

            uint32_t Bf[8][4];
            #pragma unroll
            for (int k = 0; k < 8; k++) {
                uint4 u = *reinterpret_cast<const uint4*>(Bs + (kb + k) * TW + tx * 4);
                Bf[k][0] = u.x; Bf[k][1] = u.y; Bf[k][2] = u.z; Bf[k][3] = u.w;
            }

            #pragma unroll
            for (int rr = 0; rr < 2; rr++) {
                uint32_t Af[8][4];
                #pragma unroll
                for (int k = 0; k < 8; k++) {
                    uint4 u = *reinterpret_cast<const uint4*>(
                        As + (kb + k) * TW + ty * 8 + rr * 4);
                    Af[k][0] = u.x; Af[k][1] = u.y; Af[k][2] = u.z; Af[k][3] = u.w;
                }
                #pragma unroll
                for (int r = 0; r < 4; r++) {
                    #pragma unroll
                    for (int cp = 0; cp < 2; cp++) {
                        uint32_t tt[2];
                        #pragma unroll
                        for (int h = 0; h < 2; h++) {
                            const int cc = cp * 2 + h;
                            const uint32_t x0 = Af[0][r] ^ Bf[0][cc];
                            const uint32_t x1 = Af[1][r] ^ Bf[1][cc];
                            const uint32_t x2 = Af[2][r] ^ Bf[2][cc];
                            const uint32_t x3 = Af[3][r] ^ Bf[3][cc];
                            const uint32_t x4 = Af[4][r] ^ Bf[4][cc];
                            const uint32_t x5 = Af[5][r] ^ Bf[5][cc];
                            const uint32_t x6 = Af[6][r] ^ Bf[6][cc];
                            const uint32_t x7 = Af[7][r] ^ Bf[7][cc];
                            const uint32_t s0 = xor3(x0, x1, x2), c0 = maj3(x0, x1, x2);
                            const uint32_t s1 = xor3(x3, x4, x5), c1 = maj3(x3, x4, x5);
                            const uint32_t s2 = x6 ^ x7,          c2 = x6 & x7;
                            const uint32_t S  = xor3(s0, s1, s2), C3 = maj3(s0, s1, s2);
                            const uint32_t S2 = xor3(c0, c1, c2), C2 = maj3(c0, c1, c2);
                            tt[h] = __popc(S)
                                  + 2 * (__popc(S2) + __popc(C3))
                                  + 4 * __popc(C2);
                        }
                        accP[rr * 4 + r][cp] += tt[0] + (tt[1] << 16);
                    }
                }
            }
        }
        __syncthreads();
    }

    // -------- epilogue: out = 4096 - 2*count + bias --------
    const int rb = mBase + ty * 8;
    const int cb = nBase + tx * 4;
    const float4 bias0 = *reinterpret_cast<const float4*>(bias + cb);

    #pragma unroll
    for (int r = 0; r < 8; r++) {
        const int c0 = (int)(accP[r][0] & 0xFFFF), c1 = (int)(accP[r][0] >> 16);
        const int c2 = (int)(accP[r][1] & 0xFFFF), c3 = (int)(accP[r][1] >> 16);
        float4 o0;
        o0.x = (float)(KDIM - 2 * c0) + bias0.x;
        o0.y = (float)(KDIM - 2 * c1) + bias0.y;
        o0.z = (float)(KDIM - 2 * c2) + bias0.z;
        o0.w = (float)(KDIM - 2 * c3) + bias0.w;
        *reinterpret_cast<float4*>(out + (size_t)(rb + r) * ODIM + cb) = o0;
    }
}

// ---------------- host ----------------
extern "C" void kernel_launch(void* const* d_in, const int* in_sizes, int n_in,
                              void* d_out, int out_size) {
    const float* x    = (const float*)d_in[0];
    const float* w    = (const float*)d_in[1];
    const float* bias = (const float*)d_in[2];
    float* out = (float*)d_out;

    void* pxT = nullptr; cudaGetSymbolAddress(&pxT, g_xT);
    void* pwT = nullptr; cudaGetSymbolAddress(&pwT, g_wT);

    // fused pack: blocks [0,2048) -> x, [2048,3072) -> w
    pack_bits<<<3072, 256>>>((const float4*)x, (uint32_t*)pxT,
                             (const float4*)w, (uint32_t*)pwT);

    cudaFuncSetAttribute(xnor_gemm, cudaFuncAttributeMaxDynamicSharedMemorySize, SMEM_BYTES);

    const int grid = (NROWS / TW) * (ODIM / TW);   // 2048
    xnor_gemm<<<grid, NTHR, SMEM_BYTES>>>((const uint32_t*)pxT, (const uint32_t*)pwT,
                                          bias, out);
}

// round 15
// speedup vs baseline: 1.2470x; 1.0098x over previous
#include <cuda_runtime.h>
#include <cstdint>

// ---------------- problem constants ----------------
#define NROWS   8192
#define KDIM    4096
#define ODIM    4096
#define KW      (KDIM / 32)        // 128 words of packed sign bits per row
#define TW      128                // output tile: 128 x 128
#define CHUNK   32                 // k-words per pipeline stage
#define KITC    (KW / CHUNK)       // 4 chunks
#define NTHR    512                // 16 warps -> 4 per SMSP
#define XST_WORDS (2 * CHUNK * TW)              // A + B: 8192 words = 32KB
#define SMEM_BYTES  (3 * XST_WORDS * 4)         // 98304

// ---------------- device scratch (allocation-free rule) ----------------
__device__ __align__(1024) uint32_t g_xT[(size_t)KW * NROWS];
__device__ __align__(1024) uint32_t g_wT[(size_t)KW * ODIM];

// ---------------- helpers ----------------
__device__ __forceinline__ uint32_t smem_u32(const void* p) {
    uint32_t a;
    asm("{ .reg .u64 t; cvta.to.shared.u64 t, %1; cvt.u32.u64 %0, t; }" : "=r"(a) : "l"(p));
    return a;
}
#define CP_ASYNC16(dst, src) \
    asm volatile("cp.async.cg.shared.global [%0], [%1], 16;" :: "r"(dst), "l"(src))
#define CP_COMMIT() asm volatile("cp.async.commit_group;" ::: "memory")
#define CP_WAIT1()  asm volatile("cp.async.wait_group 1;"  ::: "memory")

__device__ __forceinline__ uint32_t xor3(uint32_t a, uint32_t b, uint32_t c) {
    uint32_t d; asm("lop3.b32 %0, %1, %2, %3, 0x96;" : "=r"(d) : "r"(a), "r"(b), "r"(c));
    return d;
}
__device__ __forceinline__ uint32_t maj3(uint32_t a, uint32_t b, uint32_t c) {
    uint32_t d; asm("lop3.b32 %0, %1, %2, %3, 0xE8;" : "=r"(d) : "r"(a), "r"(b), "r"(c));
    return d;
}

// ------- pack: f32 -> 1 bit sign, transposed [kw][row]; x and w fused -------
__global__ void __launch_bounds__(256) pack_bits(const float4* __restrict__ x,
                                                 uint32_t* __restrict__ xT,
                                                 const float4* __restrict__ w,
                                                 uint32_t* __restrict__ wT) {
    const int b = blockIdx.x;
    const float4* in;
    uint32_t* outT;
    int nhs, lb;
    if (b < 2048) { in = x; outT = xT; nhs = 12; lb = b; }          // 8192 rows
    else          { in = w; outT = wT; nhs = 11; lb = b - 2048; }   // 4096 rows
    const int idx = lb * 256 + threadIdx.x;          // word-pair index
    const int kw  = idx >> nhs;
    const int n   = (idx & ((1 << nhs) - 1)) * 2;

    uint32_t wo[2];
    #pragma unroll
    for (int rr = 0; rr < 2; rr++) {
        const float4* p = in + (size_t)(n + rr) * (KDIM / 4) + kw * 8;
        uint32_t v = 0;
        #pragma unroll
        for (int j = 0; j < 8; j++) {
            float4 f = p[j];
            v |= (__float_as_uint(f.x) >> 31) << (4 * j);
            v |= (__float_as_uint(f.y) >> 31) << (4 * j + 1);
            v |= (__float_as_uint(f.z) >> 31) << (4 * j + 2);
            v |= (__float_as_uint(f.w) >> 31) << (4 * j + 3);
        }
        wo[rr] = v;
    }
    *reinterpret_cast<uint2*>(outT + (size_t)kw * (2 << nhs) + n) = make_uint2(wo[0], wo[1]);
}

// --- XNOR GEMM: CSA 8->4, 512 thr, 1 barrier/stage, CHUNK=32 x 3 stages ---
// out[n][o] = 4096 - 2 * sum_kw popc(xT[kw][n] ^ wT[kw][o]) + bias[o]
__global__ void __launch_bounds__(NTHR, 1) xnor_gemm(
    const uint32_t* __restrict__ xT, const uint32_t* __restrict__ wT,
    const float* __restrict__ bias, float* __restrict__ out)
{
    extern __shared__ __align__(16) uint32_t sm[];
    const uint32_t smBase = smem_u32(sm);
    const int tid = threadIdx.x;
    const int tx  = tid & 31;        // 32 col groups of 4
    const int ty  = tid >> 5;        // 16 row groups of 8
    const int mt  = blockIdx.x & 63;
    const int nt  = blockIdx.x >> 6;
    const int mBase = mt * TW;
    const int nBase = nt * TW;

    auto load_stage = [&](int s, int c) {
        #pragma unroll
        for (int k = 0; k < 4; k++) {
            const int ch  = tid + k * NTHR;      // 0..2047 chunks of 16B
            const int tsr = ch >> 10;            // 0 = A, 1 = B
            const int rem = ch & 1023;
            const int kw  = rem >> 5;            // 0..31
            const int nq  = rem & 31;
            const uint32_t* gsrc = tsr
                ? (wT + (size_t)(c * CHUNK + kw) * ODIM  + nBase + nq * 4)
                : (xT + (size_t)(c * CHUNK + kw) * NROWS + mBase + nq * 4);
            const uint32_t dst = smBase +
                (uint32_t)((s * XST_WORDS + tsr * (CHUNK * TW) + kw * TW + nq * 4) * 4);
            CP_ASYNC16(dst, gsrc);
        }
    };

    // packed u16x2 accumulators: [row][colpair] (counts <= 4096 fit u16)
    uint32_t accP[8][2];
    #pragma unroll
    for (int r = 0; r < 8; r++) { accP[r][0] = 0; accP[r][1] = 0; }

    // prologue: 2 stages in flight
    load_stage(0, 0); CP_COMMIT();
    load_stage(1, 1); CP_COMMIT();

    #pragma unroll 1
    for (int c = 0; c < KITC; c++) {
        CP_WAIT1();                  // stage c complete (<=1 newer pending)
        __syncthreads();             // (a) stage c visible to all
                                     // (b) all warps done reading stage c-1's slot
        const int cl = c + 2;        //     -> safe to overwrite slot (c+2)%3
        if (cl < KITC) load_stage(cl % 3, cl);
        CP_COMMIT();

        const uint32_t* As = sm + (c % 3) * XST_WORDS;
        const uint32_t* Bs = As + CHUNK * TW;

        // four groups of 8 k-words, each compressed 8 -> 4 popc via CSA tree
        #pragma unroll
        for (int g = 0; g < 4; g++) {
            const int kb = g * 8;

            uint32_t Bf[8][4];
            #pragma unroll
            for (int k = 0; k < 8; k++) {
                uint4 u = *reinterpret_cast<const uint4*>(Bs + (kb + k) * TW + tx * 4);
                Bf[k][0] = u.x; Bf[k][1] = u.y; Bf[k][2] = u.z; Bf[k][3] = u.w;
            }

            #pragma unroll
            for (int rr = 0; rr < 2; rr++) {
                uint32_t Af[8][4];
                #pragma unroll
                for (int k = 0; k < 8; k++) {
                    uint4 u = *reinterpret_cast<const uint4*>(
                        As + (kb + k) * TW + ty * 8 + rr * 4);
                    Af[k][0] = u.x; Af[k][1] = u.y; Af[k][2] = u.z; Af[k][3] = u.w;
                }
                #pragma unroll
                for (int r = 0; r < 4; r++) {
                    #pragma unroll
                    for (int cp = 0; cp < 2; cp++) {
                        uint32_t tt[2];
                        #pragma unroll
                        for (int h = 0; h < 2; h++) {
                            const int cc = cp * 2 + h;
                            const uint32_t x0 = Af[0][r] ^ Bf[0][cc];
                            const uint32_t x1 = Af[1][r] ^ Bf[1][cc];
                            const uint32_t x2 = Af[2][r] ^ Bf[2][cc];
                            const uint32_t x3 = Af[3][r] ^ Bf[3][cc];
                            const uint32_t x4 = Af[4][r] ^ Bf[4][cc];
                            const uint32_t x5 = Af[5][r] ^ Bf[5][cc];
                            const uint32_t x6 = Af[6][r] ^ Bf[6][cc];
                            const uint32_t x7 = Af[7][r] ^ Bf[7][cc];
                            const uint32_t s0 = xor3(x0, x1, x2), c0 = maj3(x0, x1, x2);
                            const uint32_t s1 = xor3(x3, x4, x5), c1 = maj3(x3, x4, x5);
                            const uint32_t s2 = x6 ^ x7,          c2 = x6 & x7;
                            const uint32_t S  = xor3(s0, s1, s2), C3 = maj3(s0, s1, s2);
                            const uint32_t S2 = xor3(c0, c1, c2), C2 = maj3(c0, c1, c2);
                            tt[h] = __popc(S)
                                  + 2 * (__popc(S2) + __popc(C3))
                                  + 4 * __popc(C2);
                        }
                        accP[rr * 4 + r][cp] += tt[0] + (tt[1] << 16);
                    }
                }
            }
        }
    }

    // -------- epilogue: out = 4096 - 2*count + bias --------
    const int rb = mBase + ty * 8;
    const int cb = nBase + tx * 4;
    const float4 bias0 = *reinterpret_cast<const float4*>(bias + cb);

    #pragma unroll
    for (int r = 0; r < 8; r++) {
        const int c0 = (int)(accP[r][0] & 0xFFFF), c1 = (int)(accP[r][0] >> 16);
        const int c2 = (int)(accP[r][1] & 0xFFFF), c3 = (int)(accP[r][1] >> 16);
        float4 o0;
        o0.x = (float)(KDIM - 2 * c0) + bias0.x;
        o0.y = (float)(KDIM - 2 * c1) + bias0.y;
        o0.z = (float)(KDIM - 2 * c2) + bias0.z;
        o0.w = (float)(KDIM - 2 * c3) + bias0.w;
        *reinterpret_cast<float4*>(out + (size_t)(rb + r) * ODIM + cb) = o0;
    }
}

// ---------------- host ----------------
extern "C" void kernel_launch(void* const* d_in, const int* in_sizes, int n_in,
                              void* d_out, int out_size) {
    const float* x    = (const float*)d_in[0];
    const float* w    = (const float*)d_in[1];
    const float* bias = (const float*)d_in[2];
    float* out = (float*)d_out;

    void* pxT = nullptr; cudaGetSymbolAddress(&pxT, g_xT);
    void* pwT = nullptr; cudaGetSymbolAddress(&pwT, g_wT);

    // fused pack: blocks [0,2048) -> x, [2048,3072) -> w
    pack_bits<<<3072, 256>>>((const float4*)x, (uint32_t*)pxT,
                             (const float4*)w, (uint32_t*)pwT);

    cudaFuncSetAttribute(xnor_gemm, cudaFuncAttributeMaxDynamicSharedMemorySize, SMEM_BYTES);

    const int grid = (NROWS / TW) * (ODIM / TW);   // 2048
    xnor_gemm<<<grid, NTHR, SMEM_BYTES>>>((const uint32_t*)pxT, (const uint32_t*)pwT,
                                          bias, out);
}

// round 16
// speedup vs baseline: 1.2970x; 1.0401x over previous
#include <cuda_runtime.h>
#include <cstdint>

// ---------------- problem constants ----------------
#define NROWS   8192
#define KDIM    4096
#define ODIM    4096
#define KW      (KDIM / 32)        // 128 words of packed sign bits per row
#define TW      128                // output tile: 128 x 128
#define NTILES  ((NROWS / TW) * (ODIM / TW))   // 2048
#define CHUNK   32                 // k-words per pipeline stage
#define KITC    (KW / CHUNK)       // 4 chunks per tile
#define NTHR    512                // 16 warps -> 4 per SMSP
#define GRID    148                // persistent: 1 CTA per SM
#define XST_WORDS (2 * CHUNK * TW)              // A + B: 8192 words = 32KB
#define SMEM_BYTES  (3 * XST_WORDS * 4)         // 98304

// ---------------- device scratch (allocation-free rule) ----------------
__device__ __align__(1024) uint32_t g_xT[(size_t)KW * NROWS];
__device__ __align__(1024) uint32_t g_wT[(size_t)KW * ODIM];

// ---------------- helpers ----------------
__device__ __forceinline__ uint32_t smem_u32(const void* p) {
    uint32_t a;
    asm("{ .reg .u64 t; cvta.to.shared.u64 t, %1; cvt.u32.u64 %0, t; }" : "=r"(a) : "l"(p));
    return a;
}
#define CP_ASYNC16(dst, src) \
    asm volatile("cp.async.cg.shared.global [%0], [%1], 16;" :: "r"(dst), "l"(src))
#define CP_COMMIT() asm volatile("cp.async.commit_group;" ::: "memory")
#define CP_WAIT1()  asm volatile("cp.async.wait_group 1;"  ::: "memory")

__device__ __forceinline__ uint32_t xor3(uint32_t a, uint32_t b, uint32_t c) {
    uint32_t d; asm("lop3.b32 %0, %1, %2, %3, 0x96;" : "=r"(d) : "r"(a), "r"(b), "r"(c));
    return d;
}
__device__ __forceinline__ uint32_t maj3(uint32_t a, uint32_t b, uint32_t c) {
    uint32_t d; asm("lop3.b32 %0, %1, %2, %3, 0xE8;" : "=r"(d) : "r"(a), "r"(b), "r"(c));
    return d;
}

// ------- pack: f32 -> 1 bit sign, transposed [kw][row]; x and w fused -------
__global__ void __launch_bounds__(256) pack_bits(const float4* __restrict__ x,
                                                 uint32_t* __restrict__ xT,
                                                 const float4* __restrict__ w,
                                                 uint32_t* __restrict__ wT) {
    const int b = blockIdx.x;
    const float4* in;
    uint32_t* outT;
    int nhs, lb;
    if (b < 2048) { in = x; outT = xT; nhs = 12; lb = b; }          // 8192 rows
    else          { in = w; outT = wT; nhs = 11; lb = b - 2048; }   // 4096 rows
    const int idx = lb * 256 + threadIdx.x;          // word-pair index
    const int kw  = idx >> nhs;
    const int n   = (idx & ((1 << nhs) - 1)) * 2;

    uint32_t wo[2];
    #pragma unroll
    for (int rr = 0; rr < 2; rr++) {
        const float4* p = in + (size_t)(n + rr) * (KDIM / 4) + kw * 8;
        uint32_t v = 0;
        #pragma unroll
        for (int j = 0; j < 8; j++) {
            float4 f = p[j];
            v |= (__float_as_uint(f.x) >> 31) << (4 * j);
            v |= (__float_as_uint(f.y) >> 31) << (4 * j + 1);
            v |= (__float_as_uint(f.z) >> 31) << (4 * j + 2);
            v |= (__float_as_uint(f.w) >> 31) << (4 * j + 3);
        }
        wo[rr] = v;
    }
    *reinterpret_cast<uint2*>(outT + (size_t)kw * (2 << nhs) + n) = make_uint2(wo[0], wo[1]);
}

// --- persistent XNOR GEMM: CSA 8->4, continuous 3-slot ring across tiles ---
// out[n][o] = 4096 - 2 * sum_kw popc(xT[kw][n] ^ wT[kw][o]) + bias[o]
__global__ void __launch_bounds__(NTHR, 1) xnor_gemm(
    const uint32_t* __restrict__ xT, const uint32_t* __restrict__ wT,
    const float* __restrict__ bias, float* __restrict__ out)
{
    extern __shared__ __align__(16) uint32_t sm[];
    const uint32_t smBase = smem_u32(sm);
    const int tid = threadIdx.x;
    const int tx  = tid & 31;        // 32 col groups of 4
    const int ty  = tid >> 5;        // 16 row groups of 8
    const int bid = blockIdx.x;

    // my tiles: bid, bid+GRID, ... ; flat stage counter gs over all my tiles
    const int myN = (NTILES - bid + GRID - 1) / GRID;
    const int S   = myN * KITC;

    // load one stage: gs -> (tile, chunk)
    auto stage_load = [&](int slot, int gs) {
        const int t  = bid + (gs >> 2) * GRID;   // KITC = 4
        const int c  = gs & 3;
        const int mB = (t & 63) * TW;
        const int nB = (t >> 6) * TW;
        #pragma unroll
        for (int k = 0; k < 4; k++) {
            const int ch  = tid + k * NTHR;      // 0..2047 chunks of 16B
            const int tsr = ch >> 10;            // 0 = A, 1 = B
            const int rem = ch & 1023;
            const int kw  = rem >> 5;            // 0..31
            const int nq  = rem & 31;
            const uint32_t* gsrc = tsr
                ? (wT + (size_t)(c * CHUNK + kw) * ODIM  + nB + nq * 4)
                : (xT + (size_t)(c * CHUNK + kw) * NROWS + mB + nq * 4);
            const uint32_t dst = smBase +
                (uint32_t)((slot * XST_WORDS + tsr * (CHUNK * TW) + kw * TW + nq * 4) * 4);
            CP_ASYNC16(dst, gsrc);
        }
    };

    // packed u16x2 accumulators: [row][colpair] (counts <= 4096 fit u16)
    uint32_t accP[8][2];
    #pragma unroll
    for (int r = 0; r < 8; r++) { accP[r][0] = 0; accP[r][1] = 0; }

    // prologue: 2 stages in flight (once per CTA, not per tile)
    stage_load(0, 0); CP_COMMIT();
    if (S > 1) stage_load(1, 1);
    CP_COMMIT();

    #pragma unroll 1
    for (int gs = 0; gs < S; gs++) {
        CP_WAIT1();                  // stage gs complete (<=1 newer pending)
        __syncthreads();             // visible to all; prev slot fully read
        const int gl = gs + 2;
        if (gl < S) stage_load(gl % 3, gl);
        CP_COMMIT();

        const uint32_t* As = sm + (gs % 3) * XST_WORDS;
        const uint32_t* Bs = As + CHUNK * TW;

        // four groups of 8 k-words, each compressed 8 -> 4 popc via CSA tree
        #pragma unroll
        for (int g = 0; g < 4; g++) {
            const int kb = g * 8;

            uint32_t Bf[8][4];
            #pragma unroll
            for (int k = 0; k < 8; k++) {
                uint4 u = *reinterpret_cast<const uint4*>(Bs + (kb + k) * TW + tx * 4);
                Bf[k][0] = u.x; Bf[k][1] = u.y; Bf[k][2] = u.z; Bf[k][3] = u.w;
            }

            #pragma unroll
            for (int rr = 0; rr < 2; rr++) {
                uint32_t Af[8][4];
                #pragma unroll
                for (int k = 0; k < 8; k++) {
                    uint4 u = *reinterpret_cast<const uint4*>(
                        As + (kb + k) * TW + ty * 8 + rr * 4);
                    Af[k][0] = u.x; Af[k][1] = u.y; Af[k][2] = u.z; Af[k][3] = u.w;
                }
                #pragma unroll
                for (int r = 0; r < 4; r++) {
                    #pragma unroll
                    for (int cp = 0; cp < 2; cp++) {
                        uint32_t tt[2];
                        #pragma unroll
                        for (int h = 0; h < 2; h++) {
                            const int cc = cp * 2 + h;
                            const uint32_t x0 = Af[0][r] ^ Bf[0][cc];
                            const uint32_t x1 = Af[1][r] ^ Bf[1][cc];
                            const uint32_t x2 = Af[2][r] ^ Bf[2][cc];
                            const uint32_t x3 = Af[3][r] ^ Bf[3][cc];
                            const uint32_t x4 = Af[4][r] ^ Bf[4][cc];
                            const uint32_t x5 = Af[5][r] ^ Bf[5][cc];
                            const uint32_t x6 = Af[6][r] ^ Bf[6][cc];
                            const uint32_t x7 = Af[7][r] ^ Bf[7][cc];
                            const uint32_t s0 = xor3(x0, x1, x2), c0 = maj3(x0, x1, x2);
                            const uint32_t s1 = xor3(x3, x4, x5), c1 = maj3(x3, x4, x5);
                            const uint32_t s2 = x6 ^ x7,          c2 = x6 & x7;
                            const uint32_t S_  = xor3(s0, s1, s2), C3 = maj3(s0, s1, s2);
                            const uint32_t S2 = xor3(c0, c1, c2), C2 = maj3(c0, c1, c2);
                            tt[h] = __popc(S_)
                                  + 2 * (__popc(S2) + __popc(C3))
                                  + 4 * __popc(C2);
                        }
                        accP[rr * 4 + r][cp] += tt[0] + (tt[1] << 16);
                    }
                }
            }
        }

        // tile boundary: epilogue + accumulator reset (loads already in flight)
        if ((gs & 3) == 3) {
            const int t  = bid + (gs >> 2) * GRID;
            const int rb = (t & 63) * TW + ty * 8;
            const int cb = (t >> 6) * TW + tx * 4;
            const float4 bias0 = *reinterpret_cast<const float4*>(bias + cb);
            #pragma unroll
            for (int r = 0; r < 8; r++) {
                const int c0 = (int)(accP[r][0] & 0xFFFF), c1 = (int)(accP[r][0] >> 16);
                const int c2 = (int)(accP[r][1] & 0xFFFF), c3 = (int)(accP[r][1] >> 16);
                float4 o0;
                o0.x = (float)(KDIM - 2 * c0) + bias0.x;
                o0.y = (float)(KDIM - 2 * c1) + bias0.y;
                o0.z = (float)(KDIM - 2 * c2) + bias0.z;
                o0.w = (float)(KDIM - 2 * c3) + bias0.w;
                *reinterpret_cast<float4*>(out + (size_t)(rb + r) * ODIM + cb) = o0;
                accP[r][0] = 0; accP[r][1] = 0;
            }
        }
    }
}

// ---------------- host ----------------
extern "C" void kernel_launch(void* const* d_in, const int* in_sizes, int n_in,
                              void* d_out, int out_size) {
    const float* x    = (const float*)d_in[0];
    const float* w    = (const float*)d_in[1];
    const float* bias = (const float*)d_in[2];
    float* out = (float*)d_out;

    void* pxT = nullptr; cudaGetSymbolAddress(&pxT, g_xT);
    void* pwT = nullptr; cudaGetSymbolAddress(&pwT, g_wT);

    // fused pack: blocks [0,2048) -> x, [2048,3072) -> w
    pack_bits<<<3072, 256>>>((const float4*)x, (uint32_t*)pxT,
                             (const float4*)w, (uint32_t*)pwT);

    cudaFuncSetAttribute(xnor_gemm, cudaFuncAttributeMaxDynamicSharedMemorySize, SMEM_BYTES);

    xnor_gemm<<<GRID, NTHR, SMEM_BYTES>>>((const uint32_t*)pxT, (const uint32_t*)pwT,
                                          bias, out);
}